// round 16
// baseline (speedup 1.0000x reference)
#include <cuda_runtime.h>

// float32(3.4 * 3.4), exactly jnp.float32(RADIUS * RADIUS)
#define RADIUS2 11.559999465942383f
#define NSAMPLE 5
#define NBATCH  8
#define TPB     256

__device__ __forceinline__ float sq3(float x0, float x1, float x2) {
    return __fadd_rn(__fadd_rn(__fmul_rn(x0, x0), __fmul_rn(x1, x1)),
                     __fmul_rn(x2, x2));
}

// d2 = (sqq + sqk) - 2*dot; 2*dot is exact, fma(dot,-2,s) rounds once at the
// same place as the reference's mul+sub -> bit-identical (validated R15).
__device__ __forceinline__ float dist2(float qx, float qy, float qz, float sqq,
                                       float bx, float by, float bz, float sqk) {
    float dot = __fmaf_rn(qz, bz, __fmaf_rn(qy, by, __fmul_rn(qx, bx)));
    return __fmaf_rn(dot, -2.0f, __fadd_rn(sqq, sqk));
}

// Barrier-free design: TWO threads per row; each loads its 32 of the first 64
// candidates DIRECTLY from global (24x LDG.128, warp-broadcast, L1-hot) and
// builds a 32-bit hit mask; shfl_xor(1) merges. Rows with <NSAMPLE hits are
// rescued by their OWN warp (ballot -> warp-cooperative seeded scan). No
// shared memory, no __syncthreads, no atomics: warps are fully decoupled.
__global__ void __launch_bounds__(TPB)
ball_query_nosync_kernel(const float* __restrict__ x,  // [B,N,3]
                         float* __restrict__ out,      // [B,N,5]
                         int n_rows, int npb)
{
    const unsigned FULL = 0xffffffffu;
    int gtid = blockIdx.x * TPB + threadIdx.x;
    int half = gtid & 1;
    int row  = gtid >> 1;

    // Warp-uniform exit for fully out-of-range warps.
    int warp_row0 = (blockIdx.x * TPB + (threadIdx.x & ~31)) >> 1;
    if (warp_row0 >= n_rows) return;

    int rr = min(row, n_rows - 1);
    int b  = rr / npb;
    int q  = rr - b * npb;
    const float* xb = x + (long long)b * npb * 3;

    // Fast path requires: warp within one batch, npb >= 64, batch base
    // float4-aligned (offset in floats divisible by 4).
    int b_lead = __shfl_sync(FULL, b, 0);
    bool uni = __all_sync(FULL, b == b_lead);
    bool seeded = uni && (npb >= 64) &&
                  ((((long long)b_lead * npb * 3) & 3) == 0);

    float qx = xb[q * 3 + 0];
    float qy = xb[q * 3 + 1];
    float qz = xb[q * 3 + 2];
    float sqq = sq3(qx, qy, qz);

    unsigned m = 0u;
    if (seeded) {
        // This thread's 32 candidates: 384 contiguous bytes = 24 float4.
        const float4* cp = reinterpret_cast<const float4*>(xb) + half * 24;
        #pragma unroll
        for (int g = 0; g < 4; g++) {
            float4 v0 = cp[g * 6 + 0];
            float4 v1 = cp[g * 6 + 1];
            float4 v2 = cp[g * 6 + 2];
            float4 v3 = cp[g * 6 + 3];
            float4 v4 = cp[g * 6 + 4];
            float4 v5 = cp[g * 6 + 5];
            float c[8][3] = {
                {v0.x, v0.y, v0.z}, {v0.w, v1.x, v1.y},
                {v1.z, v1.w, v2.x}, {v2.y, v2.z, v2.w},
                {v3.x, v3.y, v3.z}, {v3.w, v4.x, v4.y},
                {v4.z, v4.w, v5.x}, {v5.y, v5.z, v5.w}};
            #pragma unroll
            for (int j = 0; j < 8; j++) {
                float d2 = dist2(qx, qy, qz, sqq, c[j][0], c[j][1], c[j][2],
                                 sq3(c[j][0], c[j][1], c[j][2]));
                m |= (d2 < RADIUS2) ? (1u << (g * 8 + j)) : 0u;
            }
        }
    }

    unsigned other = __shfl_xor_sync(FULL, m, 1);

    bool ok = false;
    if (half == 0 && row < n_rows) {
        unsigned long long mask = (unsigned long long)m |
                                  ((unsigned long long)other << 32);
        if (__popcll(mask) >= NSAMPLE) {
            unsigned long long t = mask;
            int i0 = __ffsll(t) - 1; t &= t - 1;
            int i1 = __ffsll(t) - 1; t &= t - 1;
            int i2 = __ffsll(t) - 1; t &= t - 1;
            int i3 = __ffsll(t) - 1; t &= t - 1;
            int i4 = __ffsll(t) - 1;
            float* o = out + (long long)row * NSAMPLE;
            o[0] = (float)i0; o[1] = (float)i1; o[2] = (float)i2;
            o[3] = (float)i3; o[4] = (float)i4;
            ok = true;
        }
    }

    // In-warp rescue of failed rows (extremely rare: ~1e-5 of rows).
    unsigned fail = __ballot_sync(FULL, (half == 0) && (row < n_rows) && !ok);
    while (fail) {
        int src = __ffs(fail) - 1;
        fail &= fail - 1;
        int frow      = __shfl_sync(FULL, row, src);
        unsigned fm0  = __shfl_sync(FULL, m, src);
        unsigned fm1  = __shfl_sync(FULL, other, src);

        int fb = frow / npb;
        int fq = frow - fb * npb;
        const float* fxb = x + (long long)fb * npb * 3;

        float fqx = fxb[fq * 3 + 0];
        float fqy = fxb[fq * 3 + 1];
        float fqz = fxb[fq * 3 + 2];
        float fsqq = sq3(fqx, fqy, fqz);

        int i0 = 0, i1 = 0, i2 = 0, i3 = 0, i4 = 0;
        int cnt = 0;
        int start = 0;

        if (seeded) {
            // Seed with staged hits (k in [0,64), ascending). Uniform across
            // the warp (fm0/fm1 identical on all lanes).
            unsigned long long t = (unsigned long long)fm0 |
                                   ((unsigned long long)fm1 << 32);
            while (t) {                // popcll(t) < NSAMPLE by construction
                int idx = __ffsll(t) - 1;
                t &= t - 1;
                if (cnt == 0) {
                    i0 = idx; i1 = idx; i2 = idx; i3 = idx; i4 = idx;
                } else if (cnt == 1) { i1 = idx;
                } else if (cnt == 2) { i2 = idx;
                } else if (cnt == 3) { i3 = idx;
                } else               { i4 = idx; }
                cnt++;
            }
            start = 64;
        }

        int lane = threadIdx.x & 31;
        for (int base = start; base < npb && cnt < NSAMPLE; base += 128) {
            unsigned mm[4];
            #pragma unroll
            for (int g = 0; g < 4; g++) {
                int k = base + g * 32 + lane;
                bool pred = false;
                if (k < npb) {
                    float bx = fxb[k * 3 + 0];
                    float by = fxb[k * 3 + 1];
                    float bz = fxb[k * 3 + 2];
                    float d2 = dist2(fqx, fqy, fqz, fsqq, bx, by, bz,
                                     sq3(bx, by, bz));
                    pred = (d2 < RADIUS2);
                }
                mm[g] = __ballot_sync(FULL, pred);
            }
            #pragma unroll
            for (int g = 0; g < 4; g++) {
                unsigned w = mm[g];
                int gb = base + g * 32;
                while (w && cnt < NSAMPLE) {
                    int idx = gb + __ffs(w) - 1;
                    w &= w - 1;
                    if (cnt == 0) {
                        i0 = idx; i1 = idx; i2 = idx; i3 = idx; i4 = idx;
                    } else if (cnt == 1) { i1 = idx;
                    } else if (cnt == 2) { i2 = idx;
                    } else if (cnt == 3) { i3 = idx;
                    } else               { i4 = idx; }
                    cnt++;
                }
            }
        }

        if ((threadIdx.x & 31) == 0) {
            float* o = out + (long long)frow * NSAMPLE;
            o[0] = (float)i0; o[1] = (float)i1; o[2] = (float)i2;
            o[3] = (float)i3; o[4] = (float)i4;
        }
    }
}

extern "C" void kernel_launch(void* const* d_in, const int* in_sizes, int n_in,
                              void* d_out, int out_size) {
    const float* x = (const float*)d_in[0];
    float* out = (float*)d_out;

    int n_rows = out_size / NSAMPLE;       // B * N query rows
    int total_pts = in_sizes[0] / 3;       // B * N points
    int npb = total_pts / NBATCH;          // N per batch

    long long total_threads = (long long)n_rows * 2;
    int blocks = (int)((total_threads + TPB - 1) / TPB);
    ball_query_nosync_kernel<<<blocks, TPB>>>(x, out, n_rows, npb);
}

// round 17
// speedup vs baseline: 2.7122x; 2.7122x over previous
#include <cuda_runtime.h>

// float32(3.4 * 3.4), exactly jnp.float32(RADIUS * RADIUS)
#define RADIUS2 11.559999465942383f
#define NSAMPLE 5
#define NBATCH  8
#define STAGE   64          // candidates staged in shared for phase 1
#define TPB     256
#define ROWS_PER_BLOCK (TPB / 2)

__device__ __forceinline__ float sq3(float x0, float x1, float x2) {
    return __fadd_rn(__fadd_rn(__fmul_rn(x0, x0), __fmul_rn(x1, x1)),
                     __fmul_rn(x2, x2));
}

__device__ __forceinline__ float dist2(float qx, float qy, float qz, float sqq,
                                       float bx, float by, float bz, float sqk) {
    float dot = __fmaf_rn(qz, bz, __fmaf_rn(qy, by, __fmul_rn(qx, bx)));
    return __fsub_rn(__fadd_rn(sqq, sqk), __fmul_rn(2.0f, dot));
}

// Phase 1 (best measured config = R13): TWO threads per row; each evaluates
// 32 of the 64 staged candidates; shfl_xor(1) merges on the even lane.
// Phase 2: warp-per-failed-row rescue, 128 candidates per iteration
// (4 groups x 32, independent loads + 4 pipelined ballots), early exit.
__global__ void __launch_bounds__(TPB)
ball_query_pair4_kernel(const float* __restrict__ x,  // [B,N,3]
                        float* __restrict__ out,      // [B,N,5]
                        int n_rows, int npb)
{
    __shared__ float4 s_pts[STAGE];
    __shared__ int    s_fail[ROWS_PER_BLOCK];
    __shared__ int    s_nfail;

    int row0  = blockIdx.x * ROWS_PER_BLOCK;
    int half  = threadIdx.x & 1;
    int row   = row0 + (threadIdx.x >> 1);
    int lane  = threadIdx.x & 31;
    int wid   = threadIdx.x >> 5;
    int nwarps = TPB >> 5;

    if (threadIdx.x == 0) s_nfail = 0;

    int last_row = min(row0 + ROWS_PER_BLOCK - 1, n_rows - 1);
    int b0 = row0 / npb;
    bool uniform = (b0 == last_row / npb) && (npb >= STAGE);

    if (uniform && threadIdx.x < STAGE) {
        const float* xb0 = x + (long long)b0 * npb * 3;
        int j = threadIdx.x;
        float bx = xb0[j * 3 + 0];
        float by = xb0[j * 3 + 1];
        float bz = xb0[j * 3 + 2];
        s_pts[j] = make_float4(bx, by, bz, sq3(bx, by, bz));
    }
    __syncthreads();

    // ---------- Phase 1 ----------
    {
        int rr = min(row, n_rows - 1);
        int q = rr - b0 * npb;                   // uniform => batch is b0
        const float* xb = x + (long long)b0 * npb * 3;

        unsigned m = 0u;
        if (uniform) {
            float qx = xb[q * 3 + 0];
            float qy = xb[q * 3 + 1];
            float qz = xb[q * 3 + 2];
            float sqq = sq3(qx, qy, qz);
            int j0 = half * 32;
            #pragma unroll
            for (int j = 0; j < 32; j++) {
                float4 p = s_pts[j0 + j];
                float d2 = dist2(qx, qy, qz, sqq, p.x, p.y, p.z, p.w);
                m |= (d2 < RADIUS2) ? (1u << j) : 0u;
            }
        }

        unsigned other = __shfl_xor_sync(0xffffffffu, m, 1);

        if (half == 0 && row < n_rows) {
            unsigned long long mask = (unsigned long long)m |
                                      ((unsigned long long)other << 32);
            if (__popcll(mask) >= NSAMPLE) {
                unsigned long long t = mask;
                int i0 = __ffsll(t) - 1; t &= t - 1;
                int i1 = __ffsll(t) - 1; t &= t - 1;
                int i2 = __ffsll(t) - 1; t &= t - 1;
                int i3 = __ffsll(t) - 1; t &= t - 1;
                int i4 = __ffsll(t) - 1;
                float* o = out + (long long)row * NSAMPLE;
                o[0] = (float)i0; o[1] = (float)i1; o[2] = (float)i2;
                o[3] = (float)i3; o[4] = (float)i4;
            } else {
                int slot = atomicAdd(&s_nfail, 1);
                s_fail[slot] = row;
            }
        }
    }
    __syncthreads();

    // ---------- Phase 2: warp-per-failed-row, 128 candidates / iteration ----
    int nf = s_nfail;
    for (int i = wid; i < nf; i += nwarps) {
        int frow = s_fail[i];
        int b = frow / npb;
        int q = frow - b * npb;
        const float* xb = x + (long long)b * npb * 3;

        float qx = xb[q * 3 + 0];
        float qy = xb[q * 3 + 1];
        float qz = xb[q * 3 + 2];
        float sqq = sq3(qx, qy, qz);

        int i0 = 0, i1 = 0, i2 = 0, i3 = 0, i4 = 0;
        int cnt = 0;

        for (int base = 0; base < npb; base += 128) {
            // Evaluate 4 independent 32-candidate groups; loads overlap.
            unsigned mm[4];
            #pragma unroll
            for (int g = 0; g < 4; g++) {
                int k = base + g * 32 + lane;
                bool pred = false;
                if (k < npb) {
                    float bx = xb[k * 3 + 0];
                    float by = xb[k * 3 + 1];
                    float bz = xb[k * 3 + 2];
                    float d2 = dist2(qx, qy, qz, sqq, bx, by, bz,
                                     sq3(bx, by, bz));
                    pred = (d2 < RADIUS2);
                }
                mm[g] = __ballot_sync(0xffffffffu, pred);
            }

            #pragma unroll
            for (int g = 0; g < 4; g++) {
                unsigned w = mm[g];
                int gb = base + g * 32;
                while (w && cnt < NSAMPLE) {
                    int idx = gb + __ffs(w) - 1;
                    w &= w - 1;
                    if (cnt == 0) {
                        i0 = idx; i1 = idx; i2 = idx; i3 = idx; i4 = idx;
                    } else if (cnt == 1) { i1 = idx;
                    } else if (cnt == 2) { i2 = idx;
                    } else if (cnt == 3) { i3 = idx;
                    } else               { i4 = idx; }
                    cnt++;
                }
            }
            if (cnt == NSAMPLE) break;
        }

        if (lane == 0) {
            float* o = out + (long long)frow * NSAMPLE;
            o[0] = (float)i0; o[1] = (float)i1; o[2] = (float)i2;
            o[3] = (float)i3; o[4] = (float)i4;
        }
    }
}

extern "C" void kernel_launch(void* const* d_in, const int* in_sizes, int n_in,
                              void* d_out, int out_size) {
    const float* x = (const float*)d_in[0];
    float* out = (float*)d_out;

    int n_rows = out_size / NSAMPLE;       // B * N query rows
    int total_pts = in_sizes[0] / 3;       // B * N points
    int npb = total_pts / NBATCH;          // N per batch

    int blocks = (n_rows + ROWS_PER_BLOCK - 1) / ROWS_PER_BLOCK;
    ball_query_pair4_kernel<<<blocks, TPB>>>(x, out, n_rows, npb);
}